// round 14
// baseline (speedup 1.0000x reference)
#include <cuda_runtime.h>
#include <cuda_fp16.h>
#include <cstdint>

#define BB 2
#define SS 2048
#define DD 1024
#define HH 16
#define HD 64
#define LOG2E 1.4426950408889634f
#define ATT_SCALE 0.125f

#define NTOK (BB * SS)
// fp16 hi/lo planes (word = f16x2 pair, k-interleaved in 8-groups)
__device__ unsigned g_xph[NTOK * (DD / 2)], g_xpl[NTOK * (DD / 2)];
__device__ unsigned g_Wph[4][DD * (DD / 2)];      // weights: hi plane only
__device__ unsigned g_Oph[NTOK * (DD / 2)], g_Opl[NTOK * (DD / 2)];
#define AW (BB * HH * SS * (HD / 2))
__device__ unsigned g_Qph_[AW], g_Qpl_[AW];
__device__ unsigned g_Kph_[AW];
// V: fp16, per (b,h): [64 d-rows][1024 j2-words, j2 interleaved in 8-groups]
__device__ unsigned g_Vt16[AW];

__device__ __forceinline__ float ex2(float x) {
    float y; asm("ex2.approx.ftz.f32 %0, %1;" : "=f"(y) : "f"(x)); return y;
}
__device__ __forceinline__ unsigned pk2h(float a, float b) {     // f16x2: lo=a, hi=b
    unsigned r; asm("cvt.rn.f16x2.f32 %0, %2, %1;" : "=r"(r) : "f"(a), "f"(b)); return r;
}
__device__ __forceinline__ void split_h(float a, float b, unsigned& wh, unsigned& wl) {
    __half ha = __float2half_rn(a), hb = __float2half_rn(b);
    wh = ((unsigned)__half_as_ushort(hb) << 16) | (unsigned)__half_as_ushort(ha);
    wl = pk2h(a - __half2float(ha), b - __half2float(hb));
}
__device__ __forceinline__ int ip32(int w) {    // logical q -> physical in 8-group
    int q = w & 7;
    return (w & ~7) | ((q & 3) * 2) | (q >> 2);
}
// f16 inputs, f32 accumulate (rt ~8)
__device__ __forceinline__ void mmah(float4& d, const unsigned* a, const unsigned* b) {
    asm volatile(
        "mma.sync.aligned.m16n8k16.row.col.f32.f16.f16.f32 "
        "{%0,%1,%2,%3}, {%4,%5,%6,%7}, {%8,%9}, {%0,%1,%2,%3};"
        : "+f"(d.x), "+f"(d.y), "+f"(d.z), "+f"(d.w)
        : "r"(a[0]), "r"(a[1]), "r"(a[2]), "r"(a[3]), "r"(b[0]), "r"(b[1]));
}
// f16 inputs, f16 accumulate (rt ~4, used for small correction terms)
__device__ __forceinline__ void mmah16(uint2& d, const unsigned* a, const unsigned* b) {
    asm volatile(
        "mma.sync.aligned.m16n8k16.row.col.f16.f16.f16.f16 "
        "{%0,%1}, {%2,%3,%4,%5}, {%6,%7}, {%0,%1};"
        : "+r"(d.x), "+r"(d.y)
        : "r"(a[0]), "r"(a[1]), "r"(a[2]), "r"(a[3]), "r"(b[0]), "r"(b[1]));
}
// fold f16x2-packed accumulator pair into float4 accumulator
__device__ __forceinline__ void fold16(float4& acc, const uint2& a2) {
    __half2 p0 = *reinterpret_cast<const __half2*>(&a2.x);
    __half2 p1 = *reinterpret_cast<const __half2*>(&a2.y);
    acc.x += __low2float(p0);  acc.y += __high2float(p0);
    acc.z += __low2float(p1);  acc.w += __high2float(p1);
}
__device__ __forceinline__ uint32_t smem_u32(const void* p) {
    uint32_t a;
    asm("{ .reg .u64 t; cvta.to.shared.u64 t, %1; cvt.u32.u64 %0, t; }" : "=r"(a) : "l"(p));
    return a;
}
__device__ __forceinline__ void cpa16(uint32_t dst, const void* src) {
    asm volatile("cp.async.cg.shared.global [%0], [%1], 16;" :: "r"(dst), "l"(src));
}
__device__ __forceinline__ void cpa_commit() {
    asm volatile("cp.async.commit_group;" ::: "memory");
}
template <int N> __device__ __forceinline__ void cpa_wait() {
    asm volatile("cp.async.wait_group %0;" :: "n"(N) : "memory");
}

// ---------------- conversion: x (hi+lo) + 4 weights (hi) ----------------------
__global__ __launch_bounds__(256) void conv_all_kernel(
    const float* __restrict__ x,
    const float* __restrict__ wq, const float* __restrict__ wk,
    const float* __restrict__ wv, const float* __restrict__ wo) {
    int y = blockIdx.y;
    if (y == 0) {
        int i = blockIdx.x * 256 + threadIdx.x;          // 2M words
        float2 v = ((const float2*)x)[i];
        unsigned h, l;
        split_h(v.x, v.y, h, l);
        int o = ip32(i);
        g_xph[o] = h; g_xpl[o] = l;
    } else {
        if (blockIdx.x >= 2048) return;                  // 512K words
        const float* w = (y == 1) ? wq : (y == 2) ? wk : (y == 3) ? wv : wo;
        int i = blockIdx.x * 256 + threadIdx.x;
        float2 v = ((const float2*)w)[i];
        __half ha = __float2half_rn(v.x), hb = __float2half_rn(v.y);
        g_Wph[y - 1][ip32(i)] =
            ((unsigned)__half_as_ushort(hb) << 16) | (unsigned)__half_as_ushort(ha);
    }
}

// - GEMM: CTA 128x256, 512 thr, warp 32x64; hh f32-acc + lh f16-acc, BK=32 -----
#define GLDW 24
#define STG 12288                       // Ah 3072 + Al 3072 + Bh 6144 (words)
#define GEMM_SMEM_BYTES 131072          // max(pipeline 98304, V-staging 131072)
#define NKB 32

// mode 0: bias+RoPE+scale+split -> Q planes (hi+lo)
// mode 1: bias+RoPE            -> K plane (hi)
// mode 2: bias, pack-transpose -> fp16 V plane (smem staged, 128x256 fp32)
// mode 3: bias, fp32           -> out
__device__ __forceinline__ void gemm_core(
    const uint4* __restrict__ Ah4, const uint4* __restrict__ Al4,
    const uint4* __restrict__ Bh4,
    const float* __restrict__ bias, const float4* __restrict__ fr4,
    int mode, float* __restrict__ outf,
    unsigned* __restrict__ oph, unsigned* __restrict__ opl)
{
    extern __shared__ unsigned dsm[];
    const uint32_t sb = smem_u32(dsm);
    const int t = threadIdx.x, lane = t & 31, w = t >> 5;
    const int g = lane >> 2, qd = lane & 3;
    const int wm = (w & 3) * 32, wn = (w >> 2) * 64;
    const int bm = blockIdx.y * 128, bn = blockIdx.x * 256;

    float4 acc[2][8];
#pragma unroll
    for (int i = 0; i < 2; i++)
#pragma unroll
        for (int j = 0; j < 8; j++) acc[i][j] = make_float4(0.f, 0.f, 0.f, 0.f);

    auto issue = [&](int kb) {
        uint32_t d0 = sb + ((kb & 1) * STG) * 4;
#pragma unroll
        for (int r = 0; r < 2; r++) {   // A hi + lo
            int idx = r * 512 + t;
            int pl = idx >> 9, row = (idx >> 2) & 127, c = idx & 3;
            cpa16(d0 + (pl * 3072 + row * GLDW + c * 4) * 4,
                  (pl ? Al4 : Ah4) + (size_t)(bm + row) * 128 + kb * 4 + c);
        }
#pragma unroll
        for (int r = 0; r < 2; r++) {   // B hi
            int idx = r * 512 + t;
            int row = idx >> 2, c = idx & 3;
            cpa16(d0 + (6144 + row * GLDW + c * 4) * 4,
                  Bh4 + (size_t)(bn + row) * 128 + kb * 4 + c);
        }
        cpa_commit();
    };

    issue(0);
    for (int kb = 0; kb < NKB; kb++) {
        cpa_wait<0>();
        __syncthreads();
        if (kb < NKB - 1) issue(kb + 1);
        const unsigned* S  = dsm + (kb & 1) * STG;
        const unsigned* Ah = S;
        const unsigned* Al = S + 3072;
        const unsigned* Bh = S + 6144;
        uint2 acc2[2][8];
#pragma unroll
        for (int i = 0; i < 2; i++)
#pragma unroll
            for (int j = 0; j < 8; j++) acc2[i][j] = make_uint2(0u, 0u);
#pragma unroll
        for (int ks = 0; ks < 2; ks++) {
            unsigned ah[2][4], al[2][4];
#pragma unroll
            for (int mt = 0; mt < 2; mt++) {
                int ro = (wm + mt * 16 + g) * GLDW + ks * 8 + 2 * qd;
                uint2 h0 = *(const uint2*)(Ah + ro);
                uint2 h1 = *(const uint2*)(Ah + ro + 8 * GLDW);
                uint2 l0 = *(const uint2*)(Al + ro);
                uint2 l1 = *(const uint2*)(Al + ro + 8 * GLDW);
                ah[mt][0] = h0.x; ah[mt][2] = h0.y;
                ah[mt][1] = h1.x; ah[mt][3] = h1.y;
                al[mt][0] = l0.x; al[mt][2] = l0.y;
                al[mt][1] = l1.x; al[mt][3] = l1.y;
            }
#pragma unroll
            for (int nt = 0; nt < 8; nt++) {      // hh (f32 acc)
                int ro = (wn + nt * 8 + g) * GLDW + ks * 8 + 2 * qd;
                uint2 bv = *(const uint2*)(Bh + ro);
                unsigned bb[2] = { bv.x, bv.y };
                mmah(acc[0][nt], ah[0], bb);
                mmah(acc[1][nt], ah[1], bb);
            }
#pragma unroll
            for (int nt = 0; nt < 8; nt++) {      // lh (f16 acc, 2x rate)
                int ro = (wn + nt * 8 + g) * GLDW + ks * 8 + 2 * qd;
                uint2 bv = *(const uint2*)(Bh + ro);
                unsigned bb[2] = { bv.x, bv.y };
                mmah16(acc2[0][nt], al[0], bb);
                mmah16(acc2[1][nt], al[1], bb);
            }
        }
#pragma unroll
        for (int i = 0; i < 2; i++)
#pragma unroll
            for (int j = 0; j < 8; j++) fold16(acc[i][j], acc2[i][j]);
        __syncthreads();
    }

    const float qsc = ATT_SCALE * LOG2E;
    if (mode == 2) {
        // stage fp32 V tile (128 x 256 = 131072 B), then pack-transpose
        float* sf = (float*)dsm;
#pragma unroll
        for (int nt = 0; nt < 8; nt++) {
            int coll = wn + nt * 8 + qd * 2;
            float2 bb = *(const float2*)(bias + bn + coll);
#pragma unroll
            for (int mt = 0; mt < 2; mt++) {
                int rl = wm + mt * 16 + g;
                float4 a = acc[mt][nt];
                *(float2*)(sf + rl * 256 + coll) = make_float2(a.x + bb.x, a.y + bb.y);
                *(float2*)(sf + (rl + 8) * 256 + coll) = make_float2(a.z + bb.x, a.w + bb.y);
            }
        }
        __syncthreads();
        int b = bm >> 11;
        int j2base = (bm & 2047) >> 1;
#pragma unroll
        for (int r = 0; r < 32; r++) {
            int idx = r * 512 + t;
            int d = idx & 63, j2l = (idx >> 6) & 63, hl = idx >> 12;
            float v0 = sf[(2 * j2l) * 256 + hl * 64 + d];
            float v1 = sf[(2 * j2l + 1) * 256 + hl * 64 + d];
            int hg = (bn >> 6) + hl;
            int j2g = j2base + j2l;
            int j2p = (j2g & ~7) | ((j2g & 3) * 2) | ((j2g >> 2) & 1);
            size_t gi = ((size_t)((b * HH + hg) * 64 + d)) * (SS / 2) + j2p;
            g_Vt16[gi] = pk2h(v0, v1);
        }
        return;
    }
#pragma unroll
    for (int nt = 0; nt < 8; nt++) {
        int col = bn + wn + nt * 8 + qd * 2;
        float2 bb = *(const float2*)(bias + col);
#pragma unroll
        for (int mt = 0; mt < 2; mt++) {
            int r0 = bm + wm + mt * 16 + g;
            float4 a = acc[mt][nt];
            if (mode <= 1) {
                int h = col >> 6, d2 = (col >> 1) & 31;
                int pos = ip32(d2);
#pragma unroll
                for (int rr = 0; rr < 2; rr++) {
                    int r = r0 + rr * 8;
                    float v0 = (rr ? a.z : a.x) + bb.x;
                    float v1 = (rr ? a.w : a.y) + bb.y;
                    int b = r >> 11, s = r & 2047;
                    float4 f = fr4[s * 32 + d2];
                    float xx = f.x * v0 + f.y * v1;
                    float yy = f.z * v0 + f.w * v1;
                    if (mode == 0) { xx *= qsc; yy *= qsc; }
                    unsigned hw, lw;
                    split_h(xx, yy, hw, lw);
                    size_t idx = ((size_t)((b * HH + h) * SS + s)) * 32 + pos;
                    oph[idx] = hw;
                    if (mode == 0) opl[idx] = lw;
                }
            } else {
                *(float2*)(outf + (size_t)r0 * DD + col) =
                    make_float2(a.x + bb.x, a.y + bb.y);
                *(float2*)(outf + (size_t)(r0 + 8) * DD + col) =
                    make_float2(a.z + bb.x, a.w + bb.y);
            }
        }
    }
}

__global__ __launch_bounds__(512, 1) void gemm_qkv_kernel(
    const float* __restrict__ bq, const float* __restrict__ bk,
    const float* __restrict__ bv, const float* __restrict__ freqs) {
    int z = blockIdx.z;
    const float* bias = (z == 0) ? bq : (z == 1) ? bk : bv;
    gemm_core((const uint4*)g_xph, (const uint4*)g_xpl,
              (const uint4*)g_Wph[z],
              bias, (const float4*)freqs, z, nullptr,
              (z == 0) ? g_Qph_ : g_Kph_, (z == 0) ? g_Qpl_ : nullptr);
}
__global__ __launch_bounds__(512, 1) void gemm_o_kernel(
    const float* __restrict__ bo, float* __restrict__ out) {
    gemm_core((const uint4*)g_Oph, (const uint4*)g_Opl,
              (const uint4*)g_Wph[3],
              bo, nullptr, 3, out, nullptr, nullptr);
}

// ---- Flash attention: QK hh f32-acc + ql f16-acc, PV fp16 from registers -----
#define KLD 40
#define VLD2 40
#define STA 5120            // K 2560 + V 2560 words per stage
#define V16_ 2560
#define ATT_SMEM_WORDS (2 * STA)    // 40960 B

__global__ __launch_bounds__(256, 2) void attn_tc_kernel() {
    extern __shared__ unsigned dsm[];
    const uint32_t sb = smem_u32(dsm);

    const int t = threadIdx.x, lane = t & 31, w = t >> 5;
    const int g = lane >> 2, qd = lane & 3;
    const int qb = blockIdx.x, bh = blockIdx.y;
    const int b = bh >> 4, h = bh & 15;

    const uint4* Qh4 = (const uint4*)g_Qph_ + ((size_t)(b * HH + h) * SS + qb * 128) * 8;
    const uint4* Ql4 = (const uint4*)g_Qpl_ + ((size_t)(b * HH + h) * SS + qb * 128) * 8;
    const uint4* Kh4 = (const uint4*)g_Kph_ + (size_t)(b * HH + h) * SS * 8;
    const uint4* V16g = (const uint4*)g_Vt16 + (size_t)(b * HH + h) * 64 * 256;

    auto issue = [&](int kb) {
        uint32_t s0 = sb + ((kb & 1) * STA) * 4;
#pragma unroll
        for (int r = 0; r < 2; r++) {
            int idx = r * 256 + t;
            int row = idx >> 3, c = idx & 7;
            cpa16(s0 + (row * KLD + c * 4) * 4,
                  Kh4 + (size_t)(kb * 64 + row) * 8 + c);
        }
#pragma unroll
        for (int r = 0; r < 2; r++) {
            int idx = r * 256 + t;
            int row = idx >> 3, c = idx & 7;     // row = d 0..63
            cpa16(s0 + (V16_ + row * VLD2 + c * 4) * 4,
                  V16g + (size_t)row * 256 + kb * 8 + c);
        }
        cpa_commit();
    };

    // stage Q planes into the two stage buffers (pre-loop only)
#pragma unroll
    for (int r = 0; r < 4; r++) {
        int idx = r * 256 + t;
        int row = idx >> 3, c = idx & 7;
        *(uint4*)&dsm[row * KLD + c * 4] = Qh4[idx];
        *(uint4*)&dsm[STA + row * KLD + c * 4] = Ql4[idx];
    }
    __syncthreads();

    unsigned qh[4][4], ql[4][4];
#pragma unroll
    for (int ks = 0; ks < 4; ks++) {
        int ro = (w * 16 + g) * KLD + ks * 8 + 2 * qd;
        uint2 h0 = *(const uint2*)&dsm[ro];
        uint2 h1 = *(const uint2*)&dsm[ro + 8 * KLD];
        uint2 l0 = *(const uint2*)&dsm[STA + ro];
        uint2 l1 = *(const uint2*)&dsm[STA + ro + 8 * KLD];
        qh[ks][0] = h0.x; qh[ks][2] = h0.y;
        qh[ks][1] = h1.x; qh[ks][3] = h1.y;
        ql[ks][0] = l0.x; ql[ks][2] = l0.y;
        ql[ks][1] = l1.x; ql[ks][3] = l1.y;
    }
    __syncthreads();   // done reading Q staging before issue(0) overwrites

    float4 ofr[8];
#pragma unroll
    for (int nt = 0; nt < 8; nt++) ofr[nt] = make_float4(0.f, 0.f, 0.f, 0.f);
    float m0 = -1e30f, m1 = -1e30f, l0a = 0.f, l1a = 0.f;

    issue(0);
    for (int kb = 0; kb < SS / 64; kb++) {
        cpa_wait<0>();
        __syncthreads();
        if (kb < SS / 64 - 1) issue(kb + 1);
        const unsigned* S   = dsm + (kb & 1) * STA;
        const unsigned* Kh  = S;
        const unsigned* V16 = S + V16_;

        // S = Q K^T: qh*Kh (f32 acc) + ql*Kh (f16 acc, folded)
        float4 sfr[8];
        uint2 sfr2[8];
#pragma unroll
        for (int nt = 0; nt < 8; nt++) {
            sfr[nt] = make_float4(0.f, 0.f, 0.f, 0.f);
            sfr2[nt] = make_uint2(0u, 0u);
        }
#pragma unroll
        for (int ks = 0; ks < 4; ks++) {
#pragma unroll
            for (int nt = 0; nt < 8; nt++) {
                int ro = (nt * 8 + g) * KLD + ks * 8 + 2 * qd;
                uint2 v = *(const uint2*)&Kh[ro];
                unsigned bb[2] = { v.x, v.y };
                mmah(sfr[nt], qh[ks], bb);
            }
#pragma unroll
            for (int nt = 0; nt < 8; nt++) {
                int ro = (nt * 8 + g) * KLD + ks * 8 + 2 * qd;
                uint2 v = *(const uint2*)&Kh[ro];
                unsigned bb[2] = { v.x, v.y };
                mmah16(sfr2[nt], ql[ks], bb);
            }
        }
#pragma unroll
        for (int nt = 0; nt < 8; nt++) fold16(sfr[nt], sfr2[nt]);

        float rm0 = -1e30f, rm1 = -1e30f;
#pragma unroll
        for (int nt = 0; nt < 8; nt++) {
            rm0 = fmaxf(rm0, fmaxf(sfr[nt].x, sfr[nt].y));
            rm1 = fmaxf(rm1, fmaxf(sfr[nt].z, sfr[nt].w));
        }
        rm0 = fmaxf(rm0, __shfl_xor_sync(0xffffffffu, rm0, 1));
        rm0 = fmaxf(rm0, __shfl_xor_sync(0xffffffffu, rm0, 2));
        rm1 = fmaxf(rm1, __shfl_xor_sync(0xffffffffu, rm1, 1));
        rm1 = fmaxf(rm1, __shfl_xor_sync(0xffffffffu, rm1, 2));
        float mn0 = fmaxf(m0, rm0), mn1 = fmaxf(m1, rm1);
        float a0 = ex2(m0 - mn0), a1 = ex2(m1 - mn1);
        m0 = mn0; m1 = mn1;
        float ps0 = 0.f, ps1 = 0.f;
#pragma unroll
        for (int nt = 0; nt < 8; nt++) {
            sfr[nt].x = ex2(sfr[nt].x - mn0);
            sfr[nt].y = ex2(sfr[nt].y - mn0);
            sfr[nt].z = ex2(sfr[nt].z - mn1);
            sfr[nt].w = ex2(sfr[nt].w - mn1);
            ps0 += sfr[nt].x + sfr[nt].y;
            ps1 += sfr[nt].z + sfr[nt].w;
        }
        l0a = l0a * a0 + ps0;
        l1a = l1a * a1 + ps1;
#pragma unroll
        for (int nt = 0; nt < 8; nt++) {
            ofr[nt].x *= a0; ofr[nt].y *= a0;
            ofr[nt].z *= a1; ofr[nt].w *= a1;
        }

        // O += P V: P A-fragments packed directly from registers (f32 acc)
#pragma unroll
        for (int ks = 0; ks < 4; ks++) {
            unsigned pa[4];
            pa[0] = pk2h(sfr[2 * ks].x, sfr[2 * ks].y);
            pa[1] = pk2h(sfr[2 * ks].z, sfr[2 * ks].w);
            pa[2] = pk2h(sfr[2 * ks + 1].x, sfr[2 * ks + 1].y);
            pa[3] = pk2h(sfr[2 * ks + 1].z, sfr[2 * ks + 1].w);
#pragma unroll
            for (int nt = 0; nt < 8; nt++) {
                int ro = (nt * 8 + g) * VLD2 + ks * 8 + 2 * qd;
                uint2 v = *(const uint2*)&V16[ro];
                unsigned vb[2] = { v.x, v.y };
                mmah(ofr[nt], pa, vb);
            }
        }
        __syncthreads();   // readers done before next iter refills other buf
    }

    // epilogue: normalize, fp16-split, write O planes (token-major)
    l0a += __shfl_xor_sync(0xffffffffu, l0a, 1);
    l0a += __shfl_xor_sync(0xffffffffu, l0a, 2);
    l1a += __shfl_xor_sync(0xffffffffu, l1a, 1);
    l1a += __shfl_xor_sync(0xffffffffu, l1a, 2);
    float i0 = 1.f / l0a, i1 = 1.f / l1a;
    int row0 = qb * 128 + w * 16 + g;
#pragma unroll
    for (int nt = 0; nt < 8; nt++) {
        int d2 = nt * 4 + qd;
        int pos = ip32(d2);
        unsigned hw, lw;
        split_h(ofr[nt].x * i0, ofr[nt].y * i0, hw, lw);
        size_t ix = ((size_t)(b * SS + row0)) * 512 + h * 32 + pos;
        g_Oph[ix] = hw; g_Opl[ix] = lw;
        split_h(ofr[nt].z * i1, ofr[nt].w * i1, hw, lw);
        ix = ((size_t)(b * SS + row0 + 8)) * 512 + h * 32 + pos;
        g_Oph[ix] = hw; g_Opl[ix] = lw;
    }
}

// ---------------------------------------------------------------------------
extern "C" void kernel_launch(void* const* d_in, const int* in_sizes, int n_in,
                              void* d_out, int out_size) {
    const float* x     = (const float*)d_in[0];
    const float* freqs = (const float*)d_in[1];
    const float* Wq    = (const float*)d_in[2];
    const float* bq    = (const float*)d_in[3];
    const float* Wk    = (const float*)d_in[4];
    const float* bk    = (const float*)d_in[5];
    const float* Wv    = (const float*)d_in[6];
    const float* bv    = (const float*)d_in[7];
    const float* Wo    = (const float*)d_in[8];
    const float* bo    = (const float*)d_in[9];
    float* out = (float*)d_out;

    const size_t attn_smem = ATT_SMEM_WORDS * sizeof(unsigned);   // 40960
    cudaFuncSetAttribute(gemm_qkv_kernel, cudaFuncAttributeMaxDynamicSharedMemorySize,
                         GEMM_SMEM_BYTES);
    cudaFuncSetAttribute(gemm_o_kernel, cudaFuncAttributeMaxDynamicSharedMemorySize,
                         GEMM_SMEM_BYTES);
    cudaFuncSetAttribute(attn_tc_kernel, cudaFuncAttributeMaxDynamicSharedMemorySize,
                         (int)attn_smem);

    conv_all_kernel<<<dim3(8192, 5), 256>>>(x, Wq, Wk, Wv, Wo);
    gemm_qkv_kernel<<<dim3(DD / 256, NTOK / 128, 3), 512, GEMM_SMEM_BYTES>>>(
        bq, bk, bv, freqs);
    attn_tc_kernel<<<dim3(SS / 128, BB * HH), 256, attn_smem>>>();
    gemm_o_kernel<<<dim3(DD / 256, NTOK / 128, 1), 512, GEMM_SMEM_BYTES>>>(bo, out);
}

// round 16
// speedup vs baseline: 1.2782x; 1.2782x over previous
#include <cuda_runtime.h>
#include <cuda_fp16.h>
#include <cstdint>

#define BB 2
#define SS 2048
#define DD 1024
#define HH 16
#define HD 64
#define LOG2E 1.4426950408889634f
#define ATT_SCALE 0.125f

#define NTOK (BB * SS)
// fp16 hi/lo planes (word = f16x2 pair, k-interleaved in 8-groups)
__device__ unsigned g_xph[NTOK * (DD / 2)], g_xpl[NTOK * (DD / 2)];
__device__ unsigned g_Wph[4][DD * (DD / 2)];      // weights: hi plane only
__device__ unsigned g_Oph[NTOK * (DD / 2)], g_Opl[NTOK * (DD / 2)];
#define AW (BB * HH * SS * (HD / 2))
__device__ unsigned g_Qph_[AW];                   // Q: fp16 only
__device__ unsigned g_Kph_[AW];
// V: fp16, per (b,h): [64 d-rows][1024 j2-words, j2 interleaved in 8-groups]
__device__ unsigned g_Vt16[AW];

__device__ __forceinline__ float ex2(float x) {
    float y; asm("ex2.approx.ftz.f32 %0, %1;" : "=f"(y) : "f"(x)); return y;
}
__device__ __forceinline__ unsigned pk2h(float a, float b) {     // f16x2: lo=a, hi=b
    unsigned r; asm("cvt.rn.f16x2.f32 %0, %2, %1;" : "=r"(r) : "f"(a), "f"(b)); return r;
}
__device__ __forceinline__ void split_h(float a, float b, unsigned& wh, unsigned& wl) {
    __half ha = __float2half_rn(a), hb = __float2half_rn(b);
    wh = ((unsigned)__half_as_ushort(hb) << 16) | (unsigned)__half_as_ushort(ha);
    wl = pk2h(a - __half2float(ha), b - __half2float(hb));
}
__device__ __forceinline__ int ip32(int w) {    // logical q -> physical in 8-group
    int q = w & 7;
    return (w & ~7) | ((q & 3) * 2) | (q >> 2);
}
__device__ __forceinline__ void mmah(float4& d, const unsigned* a, const unsigned* b) {
    asm volatile(
        "mma.sync.aligned.m16n8k16.row.col.f32.f16.f16.f32 "
        "{%0,%1,%2,%3}, {%4,%5,%6,%7}, {%8,%9}, {%0,%1,%2,%3};"
        : "+f"(d.x), "+f"(d.y), "+f"(d.z), "+f"(d.w)
        : "r"(a[0]), "r"(a[1]), "r"(a[2]), "r"(a[3]), "r"(b[0]), "r"(b[1]));
}
__device__ __forceinline__ uint32_t smem_u32(const void* p) {
    uint32_t a;
    asm("{ .reg .u64 t; cvta.to.shared.u64 t, %1; cvt.u32.u64 %0, t; }" : "=r"(a) : "l"(p));
    return a;
}
__device__ __forceinline__ void cpa16(uint32_t dst, const void* src) {
    asm volatile("cp.async.cg.shared.global [%0], [%1], 16;" :: "r"(dst), "l"(src));
}
__device__ __forceinline__ void cpa_commit() {
    asm volatile("cp.async.commit_group;" ::: "memory");
}
template <int N> __device__ __forceinline__ void cpa_wait() {
    asm volatile("cp.async.wait_group %0;" :: "n"(N) : "memory");
}

// ---------------- conversion: x (hi+lo) + 4 weights (hi) ----------------------
__global__ __launch_bounds__(256) void conv_all_kernel(
    const float* __restrict__ x,
    const float* __restrict__ wq, const float* __restrict__ wk,
    const float* __restrict__ wv, const float* __restrict__ wo) {
    int y = blockIdx.y;
    if (y == 0) {
        int i = blockIdx.x * 256 + threadIdx.x;          // 2M words
        float2 v = ((const float2*)x)[i];
        unsigned h, l;
        split_h(v.x, v.y, h, l);
        int o = ip32(i);
        g_xph[o] = h; g_xpl[o] = l;
    } else {
        if (blockIdx.x >= 2048) return;                  // 512K words
        const float* w = (y == 1) ? wq : (y == 2) ? wk : (y == 3) ? wv : wo;
        int i = blockIdx.x * 256 + threadIdx.x;
        float2 v = ((const float2*)w)[i];
        __half ha = __float2half_rn(v.x), hb = __float2half_rn(v.y);
        g_Wph[y - 1][ip32(i)] =
            ((unsigned)__half_as_ushort(hb) << 16) | (unsigned)__half_as_ushort(ha);
    }
}

// --- GEMM: CTA 128x256, 512 thr, warp 32x64, 2-term fp16 (hh+lh), BK=32 -------
#define GLDW 24
#define STG 12288                       // Ah 3072 + Al 3072 + Bh 6144 (words)
#define GEMM_SMEM_BYTES 131072          // max(pipeline 98304, V-staging 131072)
#define NKB 32

// mode 0: bias+RoPE+scale -> Q plane (fp16)
// mode 1: bias+RoPE       -> K plane (fp16)
// mode 2: bias, pack-transpose -> fp16 V plane (smem staged, 128x256 fp32)
// mode 3: bias, fp32      -> out
__device__ __forceinline__ void gemm_core(
    const uint4* __restrict__ Ah4, const uint4* __restrict__ Al4,
    const uint4* __restrict__ Bh4,
    const float* __restrict__ bias, const float4* __restrict__ fr4,
    int mode, float* __restrict__ outf, unsigned* __restrict__ oph)
{
    extern __shared__ unsigned dsm[];
    const uint32_t sb = smem_u32(dsm);
    const int t = threadIdx.x, lane = t & 31, w = t >> 5;
    const int g = lane >> 2, qd = lane & 3;
    const int wm = (w & 3) * 32, wn = (w >> 2) * 64;
    const int bm = blockIdx.y * 128, bn = blockIdx.x * 256;

    float4 acc[2][8];
#pragma unroll
    for (int i = 0; i < 2; i++)
#pragma unroll
        for (int j = 0; j < 8; j++) acc[i][j] = make_float4(0.f, 0.f, 0.f, 0.f);

    auto issue = [&](int kb) {
        uint32_t d0 = sb + ((kb & 1) * STG) * 4;
#pragma unroll
        for (int r = 0; r < 2; r++) {   // A hi + lo
            int idx = r * 512 + t;
            int pl = idx >> 9, row = (idx >> 2) & 127, c = idx & 3;
            cpa16(d0 + (pl * 3072 + row * GLDW + c * 4) * 4,
                  (pl ? Al4 : Ah4) + (size_t)(bm + row) * 128 + kb * 4 + c);
        }
#pragma unroll
        for (int r = 0; r < 2; r++) {   // B hi
            int idx = r * 512 + t;
            int row = idx >> 2, c = idx & 3;
            cpa16(d0 + (6144 + row * GLDW + c * 4) * 4,
                  Bh4 + (size_t)(bn + row) * 128 + kb * 4 + c);
        }
        cpa_commit();
    };

    issue(0);
    for (int kb = 0; kb < NKB; kb++) {
        cpa_wait<0>();
        __syncthreads();
        if (kb < NKB - 1) issue(kb + 1);
        const unsigned* S  = dsm + (kb & 1) * STG;
        const unsigned* Ah = S;
        const unsigned* Al = S + 3072;
        const unsigned* Bh = S + 6144;
#pragma unroll
        for (int ks = 0; ks < 2; ks++) {
            unsigned ah[2][4], al[2][4];
#pragma unroll
            for (int mt = 0; mt < 2; mt++) {
                int ro = (wm + mt * 16 + g) * GLDW + ks * 8 + 2 * qd;
                uint2 h0 = *(const uint2*)(Ah + ro);
                uint2 h1 = *(const uint2*)(Ah + ro + 8 * GLDW);
                uint2 l0 = *(const uint2*)(Al + ro);
                uint2 l1 = *(const uint2*)(Al + ro + 8 * GLDW);
                ah[mt][0] = h0.x; ah[mt][2] = h0.y;
                ah[mt][1] = h1.x; ah[mt][3] = h1.y;
                al[mt][0] = l0.x; al[mt][2] = l0.y;
                al[mt][1] = l1.x; al[mt][3] = l1.y;
            }
            unsigned bhf[8][2];
#pragma unroll
            for (int nt = 0; nt < 8; nt++) {
                int ro = (wn + nt * 8 + g) * GLDW + ks * 8 + 2 * qd;
                uint2 bv = *(const uint2*)(Bh + ro);
                bhf[nt][0] = bv.x; bhf[nt][1] = bv.y;
            }
#pragma unroll
            for (int nt = 0; nt < 8; nt++) {      // hh
                mmah(acc[0][nt], ah[0], bhf[nt]);
                mmah(acc[1][nt], ah[1], bhf[nt]);
            }
#pragma unroll
            for (int nt = 0; nt < 8; nt++) {      // lh
                mmah(acc[0][nt], al[0], bhf[nt]);
                mmah(acc[1][nt], al[1], bhf[nt]);
            }
        }
        __syncthreads();
    }

    const float qsc = ATT_SCALE * LOG2E;
    if (mode == 2) {
        // stage fp32 V tile (128 x 256 = 131072 B), then pack-transpose
        float* sf = (float*)dsm;
#pragma unroll
        for (int nt = 0; nt < 8; nt++) {
            int coll = wn + nt * 8 + qd * 2;
            float2 bb = *(const float2*)(bias + bn + coll);
#pragma unroll
            for (int mt = 0; mt < 2; mt++) {
                int rl = wm + mt * 16 + g;
                float4 a = acc[mt][nt];
                *(float2*)(sf + rl * 256 + coll) = make_float2(a.x + bb.x, a.y + bb.y);
                *(float2*)(sf + (rl + 8) * 256 + coll) = make_float2(a.z + bb.x, a.w + bb.y);
            }
        }
        __syncthreads();
        int b = bm >> 11;
        int j2base = (bm & 2047) >> 1;
#pragma unroll
        for (int r = 0; r < 32; r++) {
            int idx = r * 512 + t;
            int d = idx & 63, j2l = (idx >> 6) & 63, hl = idx >> 12;
            float v0 = sf[(2 * j2l) * 256 + hl * 64 + d];
            float v1 = sf[(2 * j2l + 1) * 256 + hl * 64 + d];
            int hg = (bn >> 6) + hl;
            int j2g = j2base + j2l;
            int j2p = (j2g & ~7) | ((j2g & 3) * 2) | ((j2g >> 2) & 1);
            size_t gi = ((size_t)((b * HH + hg) * 64 + d)) * (SS / 2) + j2p;
            g_Vt16[gi] = pk2h(v0, v1);
        }
        return;
    }
#pragma unroll
    for (int nt = 0; nt < 8; nt++) {
        int col = bn + wn + nt * 8 + qd * 2;
        float2 bb = *(const float2*)(bias + col);
#pragma unroll
        for (int mt = 0; mt < 2; mt++) {
            int r0 = bm + wm + mt * 16 + g;
            float4 a = acc[mt][nt];
            if (mode <= 1) {
                int h = col >> 6, d2 = (col >> 1) & 31;
                int pos = ip32(d2);
#pragma unroll
                for (int rr = 0; rr < 2; rr++) {
                    int r = r0 + rr * 8;
                    float v0 = (rr ? a.z : a.x) + bb.x;
                    float v1 = (rr ? a.w : a.y) + bb.y;
                    int b = r >> 11, s = r & 2047;
                    float4 f = fr4[s * 32 + d2];
                    float xx = f.x * v0 + f.y * v1;
                    float yy = f.z * v0 + f.w * v1;
                    if (mode == 0) { xx *= qsc; yy *= qsc; }
                    size_t idx = ((size_t)((b * HH + h) * SS + s)) * 32 + pos;
                    oph[idx] = pk2h(xx, yy);
                }
            } else {
                *(float2*)(outf + (size_t)r0 * DD + col) =
                    make_float2(a.x + bb.x, a.y + bb.y);
                *(float2*)(outf + (size_t)(r0 + 8) * DD + col) =
                    make_float2(a.z + bb.x, a.w + bb.y);
            }
        }
    }
}

__global__ __launch_bounds__(512, 1) void gemm_qkv_kernel(
    const float* __restrict__ bq, const float* __restrict__ bk,
    const float* __restrict__ bv, const float* __restrict__ freqs) {
    int z = blockIdx.z;
    const float* bias = (z == 0) ? bq : (z == 1) ? bk : bv;
    gemm_core((const uint4*)g_xph, (const uint4*)g_xpl,
              (const uint4*)g_Wph[z],
              bias, (const float4*)freqs, z, nullptr,
              (z == 0) ? g_Qph_ : g_Kph_);
}
__global__ __launch_bounds__(512, 1) void gemm_o_kernel(
    const float* __restrict__ bo, float* __restrict__ out) {
    gemm_core((const uint4*)g_Oph, (const uint4*)g_Opl,
              (const uint4*)g_Wph[3],
              bo, nullptr, 3, out, nullptr);
}

// ---- Flash attention: QK plain fp16, PV fp16 from registers ------------------
#define KLD 40
#define VLD2 40
#define STA 5120            // K 2560 + V 2560 words per stage
#define V16_ 2560
#define ATT_SMEM_WORDS (2 * STA)    // 40960 B

__global__ __launch_bounds__(256, 2) void attn_tc_kernel() {
    extern __shared__ unsigned dsm[];
    const uint32_t sb = smem_u32(dsm);

    const int t = threadIdx.x, lane = t & 31, w = t >> 5;
    const int g = lane >> 2, qd = lane & 3;
    const int qb = blockIdx.x, bh = blockIdx.y;
    const int b = bh >> 4, h = bh & 15;

    const uint4* Qh4 = (const uint4*)g_Qph_ + ((size_t)(b * HH + h) * SS + qb * 128) * 8;
    const uint4* Kh4 = (const uint4*)g_Kph_ + (size_t)(b * HH + h) * SS * 8;
    const uint4* V16g = (const uint4*)g_Vt16 + (size_t)(b * HH + h) * 64 * 256;

    auto issue = [&](int kb) {
        uint32_t s0 = sb + ((kb & 1) * STA) * 4;
#pragma unroll
        for (int r = 0; r < 2; r++) {
            int idx = r * 256 + t;
            int row = idx >> 3, c = idx & 7;
            cpa16(s0 + (row * KLD + c * 4) * 4,
                  Kh4 + (size_t)(kb * 64 + row) * 8 + c);
        }
#pragma unroll
        for (int r = 0; r < 2; r++) {
            int idx = r * 256 + t;
            int row = idx >> 3, c = idx & 7;     // row = d 0..63
            cpa16(s0 + (V16_ + row * VLD2 + c * 4) * 4,
                  V16g + (size_t)row * 256 + kb * 8 + c);
        }
        cpa_commit();
    };

    // stage FULL Q plane (128 rows x 8 uint4 = 1024 uint4) pre-loop only
#pragma unroll
    for (int r = 0; r < 4; r++) {
        int idx = r * 256 + t;
        int row = idx >> 3, c = idx & 7;
        *(uint4*)&dsm[row * KLD + c * 4] = Qh4[idx];
    }
    __syncthreads();

    unsigned qh[4][4];
#pragma unroll
    for (int ks = 0; ks < 4; ks++) {
        int ro = (w * 16 + g) * KLD + ks * 8 + 2 * qd;
        uint2 h0 = *(const uint2*)&dsm[ro];
        uint2 h1 = *(const uint2*)&dsm[ro + 8 * KLD];
        qh[ks][0] = h0.x; qh[ks][2] = h0.y;
        qh[ks][1] = h1.x; qh[ks][3] = h1.y;
    }
    __syncthreads();   // done reading Q staging before issue(0) overwrites

    float4 ofr[8];
#pragma unroll
    for (int nt = 0; nt < 8; nt++) ofr[nt] = make_float4(0.f, 0.f, 0.f, 0.f);
    float m0 = -1e30f, m1 = -1e30f, l0a = 0.f, l1a = 0.f;

    issue(0);
    for (int kb = 0; kb < SS / 64; kb++) {
        cpa_wait<0>();
        __syncthreads();
        if (kb < SS / 64 - 1) issue(kb + 1);
        const unsigned* S   = dsm + (kb & 1) * STA;
        const unsigned* Kh  = S;
        const unsigned* V16 = S + V16_;

        // S = Q K^T (single fp16 pass)
        float4 sfr[8];
#pragma unroll
        for (int nt = 0; nt < 8; nt++) sfr[nt] = make_float4(0.f, 0.f, 0.f, 0.f);
#pragma unroll
        for (int ks = 0; ks < 4; ks++) {
#pragma unroll
            for (int nt = 0; nt < 8; nt++) {
                int ro = (nt * 8 + g) * KLD + ks * 8 + 2 * qd;
                uint2 v = *(const uint2*)&Kh[ro];
                unsigned bb[2] = { v.x, v.y };
                mmah(sfr[nt], qh[ks], bb);
            }
        }

        // online softmax; p-values stay in registers
        float rm0 = -1e30f, rm1 = -1e30f;
#pragma unroll
        for (int nt = 0; nt < 8; nt++) {
            rm0 = fmaxf(rm0, fmaxf(sfr[nt].x, sfr[nt].y));
            rm1 = fmaxf(rm1, fmaxf(sfr[nt].z, sfr[nt].w));
        }
        rm0 = fmaxf(rm0, __shfl_xor_sync(0xffffffffu, rm0, 1));
        rm0 = fmaxf(rm0, __shfl_xor_sync(0xffffffffu, rm0, 2));
        rm1 = fmaxf(rm1, __shfl_xor_sync(0xffffffffu, rm1, 1));
        rm1 = fmaxf(rm1, __shfl_xor_sync(0xffffffffu, rm1, 2));
        float mn0 = fmaxf(m0, rm0), mn1 = fmaxf(m1, rm1);
        float a0 = ex2(m0 - mn0), a1 = ex2(m1 - mn1);
        m0 = mn0; m1 = mn1;
        float ps0 = 0.f, ps1 = 0.f;
#pragma unroll
        for (int nt = 0; nt < 8; nt++) {
            sfr[nt].x = ex2(sfr[nt].x - mn0);
            sfr[nt].y = ex2(sfr[nt].y - mn0);
            sfr[nt].z = ex2(sfr[nt].z - mn1);
            sfr[nt].w = ex2(sfr[nt].w - mn1);
            ps0 += sfr[nt].x + sfr[nt].y;
            ps1 += sfr[nt].z + sfr[nt].w;
        }
        l0a = l0a * a0 + ps0;
        l1a = l1a * a1 + ps1;
#pragma unroll
        for (int nt = 0; nt < 8; nt++) {
            ofr[nt].x *= a0; ofr[nt].y *= a0;
            ofr[nt].z *= a1; ofr[nt].w *= a1;
        }

        // O += P V: P A-fragments packed directly from registers
#pragma unroll
        for (int ks = 0; ks < 4; ks++) {
            unsigned pa[4];
            pa[0] = pk2h(sfr[2 * ks].x, sfr[2 * ks].y);
            pa[1] = pk2h(sfr[2 * ks].z, sfr[2 * ks].w);
            pa[2] = pk2h(sfr[2 * ks + 1].x, sfr[2 * ks + 1].y);
            pa[3] = pk2h(sfr[2 * ks + 1].z, sfr[2 * ks + 1].w);
#pragma unroll
            for (int nt = 0; nt < 8; nt++) {
                int ro = (nt * 8 + g) * VLD2 + ks * 8 + 2 * qd;
                uint2 v = *(const uint2*)&V16[ro];
                unsigned vb[2] = { v.x, v.y };
                mmah(ofr[nt], pa, vb);
            }
        }
        __syncthreads();   // readers done before next iter refills other buf
    }

    // epilogue: normalize, fp16-split, write O planes (token-major)
    l0a += __shfl_xor_sync(0xffffffffu, l0a, 1);
    l0a += __shfl_xor_sync(0xffffffffu, l0a, 2);
    l1a += __shfl_xor_sync(0xffffffffu, l1a, 1);
    l1a += __shfl_xor_sync(0xffffffffu, l1a, 2);
    float i0 = 1.f / l0a, i1 = 1.f / l1a;
    int row0 = qb * 128 + w * 16 + g;
#pragma unroll
    for (int nt = 0; nt < 8; nt++) {
        int d2 = nt * 4 + qd;
        int pos = ip32(d2);
        unsigned hw, lw;
        split_h(ofr[nt].x * i0, ofr[nt].y * i0, hw, lw);
        size_t ix = ((size_t)(b * SS + row0)) * 512 + h * 32 + pos;
        g_Oph[ix] = hw; g_Opl[ix] = lw;
        split_h(ofr[nt].z * i1, ofr[nt].w * i1, hw, lw);
        ix = ((size_t)(b * SS + row0 + 8)) * 512 + h * 32 + pos;
        g_Oph[ix] = hw; g_Opl[ix] = lw;
    }
}

// ---------------------------------------------------------------------------
extern "C" void kernel_launch(void* const* d_in, const int* in_sizes, int n_in,
                              void* d_out, int out_size) {
    const float* x     = (const float*)d_in[0];
    const float* freqs = (const float*)d_in[1];
    const float* Wq    = (const float*)d_in[2];
    const float* bq    = (const float*)d_in[3];
    const float* Wk    = (const float*)d_in[4];
    const float* bk    = (const float*)d_in[5];
    const float* Wv    = (const float*)d_in[6];
    const float* bv    = (const float*)d_in[7];
    const float* Wo    = (const float*)d_in[8];
    const float* bo    = (const float*)d_in[9];
    float* out = (float*)d_out;

    const size_t attn_smem = ATT_SMEM_WORDS * sizeof(unsigned);   // 40960
    cudaFuncSetAttribute(gemm_qkv_kernel, cudaFuncAttributeMaxDynamicSharedMemorySize,
                         GEMM_SMEM_BYTES);
    cudaFuncSetAttribute(gemm_o_kernel, cudaFuncAttributeMaxDynamicSharedMemorySize,
                         GEMM_SMEM_BYTES);
    cudaFuncSetAttribute(attn_tc_kernel, cudaFuncAttributeMaxDynamicSharedMemorySize,
                         (int)attn_smem);

    conv_all_kernel<<<dim3(8192, 5), 256>>>(x, Wq, Wk, Wv, Wo);
    gemm_qkv_kernel<<<dim3(DD / 256, NTOK / 128, 3), 512, GEMM_SMEM_BYTES>>>(
        bq, bk, bv, freqs);
    attn_tc_kernel<<<dim3(SS / 128, BB * HH), 256, attn_smem>>>();
    gemm_o_kernel<<<dim3(DD / 256, NTOK / 128, 1), 512, GEMM_SMEM_BYTES>>>(bo, out);
}

// round 17
// speedup vs baseline: 1.5041x; 1.1767x over previous
#include <cuda_runtime.h>
#include <cuda_fp16.h>
#include <cstdint>

#define BB 2
#define SS 2048
#define DD 1024
#define HH 16
#define HD 64
#define LOG2E 1.4426950408889634f
#define ATT_SCALE 0.125f

#define NTOK (BB * SS)
// fp16 hi/lo planes (word = f16x2 pair, k-interleaved in 8-groups)
__device__ unsigned g_xph[NTOK * (DD / 2)], g_xpl[NTOK * (DD / 2)];
__device__ unsigned g_Wph[4][DD * (DD / 2)];      // weights: hi plane only
__device__ unsigned g_Oph[NTOK * (DD / 2)], g_Opl[NTOK * (DD / 2)];
#define AW (BB * HH * SS * (HD / 2))
__device__ unsigned g_Qph_[AW];                   // Q: fp16 only
__device__ unsigned g_Kph_[AW];
// V: fp16, per (b,h): [64 d-rows][1024 j2-words, j2 interleaved in 8-groups]
__device__ unsigned g_Vt16[AW];

__device__ __forceinline__ float ex2(float x) {
    float y; asm("ex2.approx.ftz.f32 %0, %1;" : "=f"(y) : "f"(x)); return y;
}
__device__ __forceinline__ unsigned pk2h(float a, float b) {     // f16x2: lo=a, hi=b
    unsigned r; asm("cvt.rn.f16x2.f32 %0, %2, %1;" : "=r"(r) : "f"(a), "f"(b)); return r;
}
__device__ __forceinline__ void split_h(float a, float b, unsigned& wh, unsigned& wl) {
    __half ha = __float2half_rn(a), hb = __float2half_rn(b);
    wh = ((unsigned)__half_as_ushort(hb) << 16) | (unsigned)__half_as_ushort(ha);
    wl = pk2h(a - __half2float(ha), b - __half2float(hb));
}
__device__ __forceinline__ int ip32(int w) {    // logical q -> physical in 8-group
    int q = w & 7;
    return (w & ~7) | ((q & 3) * 2) | (q >> 2);
}
__device__ __forceinline__ void mmah(float4& d, const unsigned* a, const unsigned* b) {
    asm volatile(
        "mma.sync.aligned.m16n8k16.row.col.f32.f16.f16.f32 "
        "{%0,%1,%2,%3}, {%4,%5,%6,%7}, {%8,%9}, {%0,%1,%2,%3};"
        : "+f"(d.x), "+f"(d.y), "+f"(d.z), "+f"(d.w)
        : "r"(a[0]), "r"(a[1]), "r"(a[2]), "r"(a[3]), "r"(b[0]), "r"(b[1]));
}
__device__ __forceinline__ uint32_t smem_u32(const void* p) {
    uint32_t a;
    asm("{ .reg .u64 t; cvta.to.shared.u64 t, %1; cvt.u32.u64 %0, t; }" : "=r"(a) : "l"(p));
    return a;
}
__device__ __forceinline__ void cpa16(uint32_t dst, const void* src) {
    asm volatile("cp.async.cg.shared.global [%0], [%1], 16;" :: "r"(dst), "l"(src));
}
__device__ __forceinline__ void cpa_commit() {
    asm volatile("cp.async.commit_group;" ::: "memory");
}
template <int N> __device__ __forceinline__ void cpa_wait() {
    asm volatile("cp.async.wait_group %0;" :: "n"(N) : "memory");
}

// ---------------- conversion: x (hi+lo) + 4 weights (hi) ----------------------
__global__ __launch_bounds__(256) void conv_all_kernel(
    const float* __restrict__ x,
    const float* __restrict__ wq, const float* __restrict__ wk,
    const float* __restrict__ wv, const float* __restrict__ wo) {
    int y = blockIdx.y;
    if (y == 0) {
        int i = blockIdx.x * 256 + threadIdx.x;          // 2M words
        float2 v = ((const float2*)x)[i];
        unsigned h, l;
        split_h(v.x, v.y, h, l);
        int o = ip32(i);
        g_xph[o] = h; g_xpl[o] = l;
    } else {
        if (blockIdx.x >= 2048) return;                  // 512K words
        const float* w = (y == 1) ? wq : (y == 2) ? wk : (y == 3) ? wv : wo;
        int i = blockIdx.x * 256 + threadIdx.x;
        float2 v = ((const float2*)w)[i];
        __half ha = __float2half_rn(v.x), hb = __float2half_rn(v.y);
        g_Wph[y - 1][ip32(i)] =
            ((unsigned)__half_as_ushort(hb) << 16) | (unsigned)__half_as_ushort(ha);
    }
}

// --- GEMM: CTA 128x256, 512 thr, warp 32x64; terms=1 (hh) or 2 (hh+lh) --------
#define GLDW 24
#define STG 12288                       // Ah 3072 + Al 3072 + Bh 6144 (words)
#define GEMM_SMEM_BYTES 131072          // max(pipeline 98304, V-staging 131072)
#define NKB 32

// mode 0: bias+RoPE+scale -> Q plane (fp16)
// mode 1: bias+RoPE       -> K plane (fp16)
// mode 2: bias, pack-transpose -> fp16 V plane (smem staged, 128x256 fp32)
// mode 3: bias, fp32      -> out
__device__ __forceinline__ void gemm_core(
    const uint4* __restrict__ Ah4, const uint4* __restrict__ Al4,
    const uint4* __restrict__ Bh4,
    const float* __restrict__ bias, const float4* __restrict__ fr4,
    int mode, int terms, float* __restrict__ outf, unsigned* __restrict__ oph)
{
    extern __shared__ unsigned dsm[];
    const uint32_t sb = smem_u32(dsm);
    const int t = threadIdx.x, lane = t & 31, w = t >> 5;
    const int g = lane >> 2, qd = lane & 3;
    const int wm = (w & 3) * 32, wn = (w >> 2) * 64;
    const int bm = blockIdx.y * 128, bn = blockIdx.x * 256;

    float4 acc[2][8];
#pragma unroll
    for (int i = 0; i < 2; i++)
#pragma unroll
        for (int j = 0; j < 8; j++) acc[i][j] = make_float4(0.f, 0.f, 0.f, 0.f);

    auto issue = [&](int kb) {
        uint32_t d0 = sb + ((kb & 1) * STG) * 4;
#pragma unroll
        for (int r = 0; r < 2; r++) {   // A hi (+ lo when terms==2)
            if (r == 1 && terms < 2) break;
            int idx = r * 512 + t;
            int pl = idx >> 9, row = (idx >> 2) & 127, c = idx & 3;
            cpa16(d0 + (pl * 3072 + row * GLDW + c * 4) * 4,
                  (pl ? Al4 : Ah4) + (size_t)(bm + row) * 128 + kb * 4 + c);
        }
#pragma unroll
        for (int r = 0; r < 2; r++) {   // B hi
            int idx = r * 512 + t;
            int row = idx >> 2, c = idx & 3;
            cpa16(d0 + (6144 + row * GLDW + c * 4) * 4,
                  Bh4 + (size_t)(bn + row) * 128 + kb * 4 + c);
        }
        cpa_commit();
    };

    issue(0);
    for (int kb = 0; kb < NKB; kb++) {
        cpa_wait<0>();
        __syncthreads();
        if (kb < NKB - 1) issue(kb + 1);
        const unsigned* S  = dsm + (kb & 1) * STG;
        const unsigned* Ah = S;
        const unsigned* Al = S + 3072;
        const unsigned* Bh = S + 6144;
#pragma unroll
        for (int ks = 0; ks < 2; ks++) {
            unsigned ah[2][4], al[2][4];
#pragma unroll
            for (int mt = 0; mt < 2; mt++) {
                int ro = (wm + mt * 16 + g) * GLDW + ks * 8 + 2 * qd;
                uint2 h0 = *(const uint2*)(Ah + ro);
                uint2 h1 = *(const uint2*)(Ah + ro + 8 * GLDW);
                ah[mt][0] = h0.x; ah[mt][2] = h0.y;
                ah[mt][1] = h1.x; ah[mt][3] = h1.y;
                if (terms == 2) {
                    uint2 l0 = *(const uint2*)(Al + ro);
                    uint2 l1 = *(const uint2*)(Al + ro + 8 * GLDW);
                    al[mt][0] = l0.x; al[mt][2] = l0.y;
                    al[mt][1] = l1.x; al[mt][3] = l1.y;
                }
            }
            unsigned bhf[8][2];
#pragma unroll
            for (int nt = 0; nt < 8; nt++) {
                int ro = (wn + nt * 8 + g) * GLDW + ks * 8 + 2 * qd;
                uint2 bv = *(const uint2*)(Bh + ro);
                bhf[nt][0] = bv.x; bhf[nt][1] = bv.y;
            }
#pragma unroll
            for (int nt = 0; nt < 8; nt++) {      // hh
                mmah(acc[0][nt], ah[0], bhf[nt]);
                mmah(acc[1][nt], ah[1], bhf[nt]);
            }
            if (terms == 2) {
#pragma unroll
                for (int nt = 0; nt < 8; nt++) {  // lh
                    mmah(acc[0][nt], al[0], bhf[nt]);
                    mmah(acc[1][nt], al[1], bhf[nt]);
                }
            }
        }
        __syncthreads();
    }

    const float qsc = ATT_SCALE * LOG2E;
    if (mode == 2) {
        // stage fp32 V tile (128 x 256 = 131072 B), then pack-transpose
        float* sf = (float*)dsm;
#pragma unroll
        for (int nt = 0; nt < 8; nt++) {
            int coll = wn + nt * 8 + qd * 2;
            float2 bb = *(const float2*)(bias + bn + coll);
#pragma unroll
            for (int mt = 0; mt < 2; mt++) {
                int rl = wm + mt * 16 + g;
                float4 a = acc[mt][nt];
                *(float2*)(sf + rl * 256 + coll) = make_float2(a.x + bb.x, a.y + bb.y);
                *(float2*)(sf + (rl + 8) * 256 + coll) = make_float2(a.z + bb.x, a.w + bb.y);
            }
        }
        __syncthreads();
        int b = bm >> 11;
        int j2base = (bm & 2047) >> 1;
#pragma unroll
        for (int r = 0; r < 32; r++) {
            int idx = r * 512 + t;
            int d = idx & 63, j2l = (idx >> 6) & 63, hl = idx >> 12;
            float v0 = sf[(2 * j2l) * 256 + hl * 64 + d];
            float v1 = sf[(2 * j2l + 1) * 256 + hl * 64 + d];
            int hg = (bn >> 6) + hl;
            int j2g = j2base + j2l;
            int j2p = (j2g & ~7) | ((j2g & 3) * 2) | ((j2g >> 2) & 1);
            size_t gi = ((size_t)((b * HH + hg) * 64 + d)) * (SS / 2) + j2p;
            g_Vt16[gi] = pk2h(v0, v1);
        }
        return;
    }
#pragma unroll
    for (int nt = 0; nt < 8; nt++) {
        int col = bn + wn + nt * 8 + qd * 2;
        float2 bb = *(const float2*)(bias + col);
#pragma unroll
        for (int mt = 0; mt < 2; mt++) {
            int r0 = bm + wm + mt * 16 + g;
            float4 a = acc[mt][nt];
            if (mode <= 1) {
                int h = col >> 6, d2 = (col >> 1) & 31;
                int pos = ip32(d2);
#pragma unroll
                for (int rr = 0; rr < 2; rr++) {
                    int r = r0 + rr * 8;
                    float v0 = (rr ? a.z : a.x) + bb.x;
                    float v1 = (rr ? a.w : a.y) + bb.y;
                    int b = r >> 11, s = r & 2047;
                    float4 f = fr4[s * 32 + d2];
                    float xx = f.x * v0 + f.y * v1;
                    float yy = f.z * v0 + f.w * v1;
                    if (mode == 0) { xx *= qsc; yy *= qsc; }
                    size_t idx = ((size_t)((b * HH + h) * SS + s)) * 32 + pos;
                    oph[idx] = pk2h(xx, yy);
                }
            } else {
                *(float2*)(outf + (size_t)r0 * DD + col) =
                    make_float2(a.x + bb.x, a.y + bb.y);
                *(float2*)(outf + (size_t)(r0 + 8) * DD + col) =
                    make_float2(a.z + bb.x, a.w + bb.y);
            }
        }
    }
}

__global__ __launch_bounds__(512, 1) void gemm_qkv_kernel(
    const float* __restrict__ bq, const float* __restrict__ bk,
    const float* __restrict__ bv, const float* __restrict__ freqs) {
    int z = blockIdx.z;
    const float* bias = (z == 0) ? bq : (z == 1) ? bk : bv;
    gemm_core((const uint4*)g_xph, (const uint4*)g_xpl,
              (const uint4*)g_Wph[z],
              bias, (const float4*)freqs, z, 1, nullptr,
              (z == 0) ? g_Qph_ : g_Kph_);
}
__global__ __launch_bounds__(512, 1) void gemm_o_kernel(
    const float* __restrict__ bo, float* __restrict__ out) {
    gemm_core((const uint4*)g_Oph, (const uint4*)g_Opl,
              (const uint4*)g_Wph[3],
              bo, nullptr, 3, 2, out, nullptr);
}

// ---- Flash attention: QK plain fp16, PV fp16 from registers ------------------
#define KLD 40
#define VLD2 40
#define STA 5120            // K 2560 + V 2560 words per stage
#define V16_ 2560
#define ATT_SMEM_WORDS (2 * STA)    // 40960 B

__global__ __launch_bounds__(256, 2) void attn_tc_kernel() {
    extern __shared__ unsigned dsm[];
    const uint32_t sb = smem_u32(dsm);

    const int t = threadIdx.x, lane = t & 31, w = t >> 5;
    const int g = lane >> 2, qd = lane & 3;
    const int qb = blockIdx.x, bh = blockIdx.y;
    const int b = bh >> 4, h = bh & 15;

    const uint4* Qh4 = (const uint4*)g_Qph_ + ((size_t)(b * HH + h) * SS + qb * 128) * 8;
    const uint4* Kh4 = (const uint4*)g_Kph_ + (size_t)(b * HH + h) * SS * 8;
    const uint4* V16g = (const uint4*)g_Vt16 + (size_t)(b * HH + h) * 64 * 256;

    auto issue = [&](int kb) {
        uint32_t s0 = sb + ((kb & 1) * STA) * 4;
#pragma unroll
        for (int r = 0; r < 2; r++) {
            int idx = r * 256 + t;
            int row = idx >> 3, c = idx & 7;
            cpa16(s0 + (row * KLD + c * 4) * 4,
                  Kh4 + (size_t)(kb * 64 + row) * 8 + c);
        }
#pragma unroll
        for (int r = 0; r < 2; r++) {
            int idx = r * 256 + t;
            int row = idx >> 3, c = idx & 7;     // row = d 0..63
            cpa16(s0 + (V16_ + row * VLD2 + c * 4) * 4,
                  V16g + (size_t)row * 256 + kb * 8 + c);
        }
        cpa_commit();
    };

    // stage FULL Q plane (128 rows x 8 uint4 = 1024 uint4) pre-loop only
#pragma unroll
    for (int r = 0; r < 4; r++) {
        int idx = r * 256 + t;
        int row = idx >> 3, c = idx & 7;
        *(uint4*)&dsm[row * KLD + c * 4] = Qh4[idx];
    }
    __syncthreads();

    unsigned qh[4][4];
#pragma unroll
    for (int ks = 0; ks < 4; ks++) {
        int ro = (w * 16 + g) * KLD + ks * 8 + 2 * qd;
        uint2 h0 = *(const uint2*)&dsm[ro];
        uint2 h1 = *(const uint2*)&dsm[ro + 8 * KLD];
        qh[ks][0] = h0.x; qh[ks][2] = h0.y;
        qh[ks][1] = h1.x; qh[ks][3] = h1.y;
    }
    __syncthreads();   // done reading Q staging before issue(0) overwrites

    float4 ofr[8];
#pragma unroll
    for (int nt = 0; nt < 8; nt++) ofr[nt] = make_float4(0.f, 0.f, 0.f, 0.f);
    float m0 = -1e30f, m1 = -1e30f, l0a = 0.f, l1a = 0.f;

    issue(0);
    for (int kb = 0; kb < SS / 64; kb++) {
        cpa_wait<0>();
        __syncthreads();
        if (kb < SS / 64 - 1) issue(kb + 1);
        const unsigned* S   = dsm + (kb & 1) * STA;
        const unsigned* Kh  = S;
        const unsigned* V16 = S + V16_;

        // S = Q K^T (single fp16 pass)
        float4 sfr[8];
#pragma unroll
        for (int nt = 0; nt < 8; nt++) sfr[nt] = make_float4(0.f, 0.f, 0.f, 0.f);
#pragma unroll
        for (int ks = 0; ks < 4; ks++) {
#pragma unroll
            for (int nt = 0; nt < 8; nt++) {
                int ro = (nt * 8 + g) * KLD + ks * 8 + 2 * qd;
                uint2 v = *(const uint2*)&Kh[ro];
                unsigned bb[2] = { v.x, v.y };
                mmah(sfr[nt], qh[ks], bb);
            }
        }

        // online softmax; p-values stay in registers
        float rm0 = -1e30f, rm1 = -1e30f;
#pragma unroll
        for (int nt = 0; nt < 8; nt++) {
            rm0 = fmaxf(rm0, fmaxf(sfr[nt].x, sfr[nt].y));
            rm1 = fmaxf(rm1, fmaxf(sfr[nt].z, sfr[nt].w));
        }
        rm0 = fmaxf(rm0, __shfl_xor_sync(0xffffffffu, rm0, 1));
        rm0 = fmaxf(rm0, __shfl_xor_sync(0xffffffffu, rm0, 2));
        rm1 = fmaxf(rm1, __shfl_xor_sync(0xffffffffu, rm1, 1));
        rm1 = fmaxf(rm1, __shfl_xor_sync(0xffffffffu, rm1, 2));
        float mn0 = fmaxf(m0, rm0), mn1 = fmaxf(m1, rm1);
        float a0 = ex2(m0 - mn0), a1 = ex2(m1 - mn1);
        m0 = mn0; m1 = mn1;
        float ps0 = 0.f, ps1 = 0.f;
#pragma unroll
        for (int nt = 0; nt < 8; nt++) {
            sfr[nt].x = ex2(sfr[nt].x - mn0);
            sfr[nt].y = ex2(sfr[nt].y - mn0);
            sfr[nt].z = ex2(sfr[nt].z - mn1);
            sfr[nt].w = ex2(sfr[nt].w - mn1);
            ps0 += sfr[nt].x + sfr[nt].y;
            ps1 += sfr[nt].z + sfr[nt].w;
        }
        l0a = l0a * a0 + ps0;
        l1a = l1a * a1 + ps1;
#pragma unroll
        for (int nt = 0; nt < 8; nt++) {
            ofr[nt].x *= a0; ofr[nt].y *= a0;
            ofr[nt].z *= a1; ofr[nt].w *= a1;
        }

        // O += P V: P A-fragments packed directly from registers
#pragma unroll
        for (int ks = 0; ks < 4; ks++) {
            unsigned pa[4];
            pa[0] = pk2h(sfr[2 * ks].x, sfr[2 * ks].y);
            pa[1] = pk2h(sfr[2 * ks].z, sfr[2 * ks].w);
            pa[2] = pk2h(sfr[2 * ks + 1].x, sfr[2 * ks + 1].y);
            pa[3] = pk2h(sfr[2 * ks + 1].z, sfr[2 * ks + 1].w);
#pragma unroll
            for (int nt = 0; nt < 8; nt++) {
                int ro = (nt * 8 + g) * VLD2 + ks * 8 + 2 * qd;
                uint2 v = *(const uint2*)&V16[ro];
                unsigned vb[2] = { v.x, v.y };
                mmah(ofr[nt], pa, vb);
            }
        }
        __syncthreads();   // readers done before next iter refills other buf
    }

    // epilogue: normalize, fp16-split, write O planes (token-major)
    l0a += __shfl_xor_sync(0xffffffffu, l0a, 1);
    l0a += __shfl_xor_sync(0xffffffffu, l0a, 2);
    l1a += __shfl_xor_sync(0xffffffffu, l1a, 1);
    l1a += __shfl_xor_sync(0xffffffffu, l1a, 2);
    float i0 = 1.f / l0a, i1 = 1.f / l1a;
    int row0 = qb * 128 + w * 16 + g;
#pragma unroll
    for (int nt = 0; nt < 8; nt++) {
        int d2 = nt * 4 + qd;
        int pos = ip32(d2);
        unsigned hw, lw;
        split_h(ofr[nt].x * i0, ofr[nt].y * i0, hw, lw);
        size_t ix = ((size_t)(b * SS + row0)) * 512 + h * 32 + pos;
        g_Oph[ix] = hw; g_Opl[ix] = lw;
        split_h(ofr[nt].z * i1, ofr[nt].w * i1, hw, lw);
        ix = ((size_t)(b * SS + row0 + 8)) * 512 + h * 32 + pos;
        g_Oph[ix] = hw; g_Opl[ix] = lw;
    }
}

// ---------------------------------------------------------------------------
extern "C" void kernel_launch(void* const* d_in, const int* in_sizes, int n_in,
                              void* d_out, int out_size) {
    const float* x     = (const float*)d_in[0];
    const float* freqs = (const float*)d_in[1];
    const float* Wq    = (const float*)d_in[2];
    const float* bq    = (const float*)d_in[3];
    const float* Wk    = (const float*)d_in[4];
    const float* bk    = (const float*)d_in[5];
    const float* Wv    = (const float*)d_in[6];
    const float* bv    = (const float*)d_in[7];
    const float* Wo    = (const float*)d_in[8];
    const float* bo    = (const float*)d_in[9];
    float* out = (float*)d_out;

    const size_t attn_smem = ATT_SMEM_WORDS * sizeof(unsigned);   // 40960
    cudaFuncSetAttribute(gemm_qkv_kernel, cudaFuncAttributeMaxDynamicSharedMemorySize,
                         GEMM_SMEM_BYTES);
    cudaFuncSetAttribute(gemm_o_kernel, cudaFuncAttributeMaxDynamicSharedMemorySize,
                         GEMM_SMEM_BYTES);
    cudaFuncSetAttribute(attn_tc_kernel, cudaFuncAttributeMaxDynamicSharedMemorySize,
                         (int)attn_smem);

    conv_all_kernel<<<dim3(8192, 5), 256>>>(x, Wq, Wk, Wv, Wo);
    gemm_qkv_kernel<<<dim3(DD / 256, NTOK / 128, 3), 512, GEMM_SMEM_BYTES>>>(
        bq, bk, bv, freqs);
    attn_tc_kernel<<<dim3(SS / 128, BB * HH), 256, attn_smem>>>();
    gemm_o_kernel<<<dim3(DD / 256, NTOK / 128, 1), 512, GEMM_SMEM_BYTES>>>(bo, out);
}